// round 3
// baseline (speedup 1.0000x reference)
#include <cuda_runtime.h>
#include <math.h>
#include <stdint.h>

#define N_ROWS 32768
#define M_COLS 2048
#define DIM    128
#define HEADS  8

// ---------------- scratch (__device__ globals; no allocations allowed) ----------------
__device__ float g_W[DIM * DIM];          // sum over heads of Wq
__device__ float g_bsum[DIM];             // 2 * sum over heads of bq
__device__ float g_G[M_COLS * DIM];       // (c @ W) / sqrt(DIM)
__device__ float g_beta[M_COLS];          // (c . b) / sqrt(DIM)
__device__ float g_L[(size_t)N_ROWS * M_COLS];   // logits, 256 MB
__device__ int   g_idx[N_ROWS];
__device__ float g_acc[M_COLS * DIM];

// ---------------- K0a: fold heads of Wq / bq ----------------
__global__ void __launch_bounds__(128) prep_Wb_kernel(const float* __restrict__ Wq,
                                                      const float* __restrict__ bq) {
    int i = blockIdx.x;    // output row of W (0..127)
    int j = threadIdx.x;   // col (0..127)
    float s = 0.f;
#pragma unroll
    for (int h = 0; h < HEADS; h++) s += Wq[(h * DIM + i) * DIM + j];
    g_W[i * DIM + j] = s;
    if (i == 0) {
        float t = 0.f;
#pragma unroll
        for (int h = 0; h < HEADS; h++) t += bq[h * DIM + j];
        g_bsum[j] = 2.0f * t;
    }
}

// ---------------- K0b: G = (c @ W)/sqrt(D), beta = (c . b)/sqrt(D) ----------------
__global__ void __launch_bounds__(128) prep_G_kernel(const float* __restrict__ c) {
    int m = blockIdx.x;
    int kq = threadIdx.x;
    __shared__ float cs[DIM];
    __shared__ float red[DIM];
    cs[kq] = c[m * DIM + kq];
    __syncthreads();
    const float inv = 0.08838834764831845f;  // 1/sqrt(128)
    float s = 0.f;
#pragma unroll 8
    for (int j = 0; j < DIM; j++) s = fmaf(cs[j], g_W[j * DIM + kq], s);
    g_G[m * DIM + kq] = s * inv;
    red[kq] = cs[kq] * g_bsum[kq];
    __syncthreads();
    for (int st = 64; st > 0; st >>= 1) {
        if (kq < st) red[kq] += red[kq + st];
        __syncthreads();
    }
    if (kq == 0) g_beta[m] = red[0] * inv;
}

// ---------------- K2: logits = (x1+k) @ G.T + beta  (fp32 tiled SGEMM) ----------------
#define BM 128
#define BN 128
#define BKK 32
__global__ void __launch_bounds__(256) logits_kernel(const float* __restrict__ x1,
                                                     const float* __restrict__ kk) {
    __shared__ float As[BKK][BM + 5];   // pad: conflict-free transposed stores
    __shared__ float Bs[BKK][BN + 5];
    const int bm = blockIdx.y;
    const int bn = blockIdx.x;
    const int tid = threadIdx.x;
    const int tx = tid & 15;
    const int ty = tid >> 4;
    const int row0 = bm * BM;
    const int col0 = bn * BN;

    float acc[8][8];
#pragma unroll
    for (int i = 0; i < 8; i++)
#pragma unroll
        for (int j = 0; j < 8; j++) acc[i][j] = 0.f;

    const int lr = tid >> 3;          // 0..31
    const int lk = (tid & 7) * 4;     // 0,4,..,28

    for (int k0 = 0; k0 < DIM; k0 += BKK) {
#pragma unroll
        for (int i = 0; i < 4; i++) {
            int r = lr + i * 32;
            float4 a4 = *(const float4*)(x1 + (size_t)(row0 + r) * DIM + k0 + lk);
            float4 b4 = *(const float4*)(kk + (size_t)(row0 + r) * DIM + k0 + lk);
            As[lk + 0][r] = a4.x + b4.x;
            As[lk + 1][r] = a4.y + b4.y;
            As[lk + 2][r] = a4.z + b4.z;
            As[lk + 3][r] = a4.w + b4.w;
            float4 g4 = *(const float4*)(g_G + (size_t)(col0 + r) * DIM + k0 + lk);
            Bs[lk + 0][r] = g4.x;
            Bs[lk + 1][r] = g4.y;
            Bs[lk + 2][r] = g4.z;
            Bs[lk + 3][r] = g4.w;
        }
        __syncthreads();
#pragma unroll
        for (int k = 0; k < BKK; k++) {
            float a[8], b[8];
#pragma unroll
            for (int i = 0; i < 8; i++) a[i] = As[k][ty * 8 + i];
#pragma unroll
            for (int j = 0; j < 8; j++) b[j] = Bs[k][tx * 8 + j];
#pragma unroll
            for (int i = 0; i < 8; i++)
#pragma unroll
                for (int j = 0; j < 8; j++) acc[i][j] = fmaf(a[i], b[j], acc[i][j]);
        }
        __syncthreads();
    }

    float4 bet0 = *(const float4*)(g_beta + col0 + tx * 8);
    float4 bet1 = *(const float4*)(g_beta + col0 + tx * 8 + 4);
#pragma unroll
    for (int i = 0; i < 8; i++) {
        int r = row0 + ty * 8 + i;
        float* outp = g_L + (size_t)r * M_COLS + col0 + tx * 8;
        float4 w0 = make_float4(acc[i][0] + bet0.x, acc[i][1] + bet0.y,
                                acc[i][2] + bet0.z, acc[i][3] + bet0.w);
        float4 w1 = make_float4(acc[i][4] + bet1.x, acc[i][5] + bet1.y,
                                acc[i][6] + bet1.z, acc[i][7] + bet1.w);
        *(float4*)(outp) = w0;
        *(float4*)(outp + 4) = w1;
    }
}

// ---------------- threefry2x32 (JAX, key=(0,42)), partitionable path ----------------
__device__ __forceinline__ void threefry2x32_042(uint32_t x0, uint32_t x1,
                                                 uint32_t& o0, uint32_t& o1) {
    const uint32_t KS0 = 0u, KS1 = 42u, KS2 = 0x1BD11BDAu ^ 42u;
    x0 += KS0; x1 += KS1;
#define TF_R(r) { x0 += x1; x1 = __funnelshift_l(x1, x1, r); x1 ^= x0; }
    TF_R(13) TF_R(15) TF_R(26) TF_R(6)   x0 += KS1; x1 += KS2 + 1u;
    TF_R(17) TF_R(29) TF_R(16) TF_R(24)  x0 += KS2; x1 += KS0 + 2u;
    TF_R(13) TF_R(15) TF_R(26) TF_R(6)   x0 += KS0; x1 += KS1 + 3u;
    TF_R(17) TF_R(29) TF_R(16) TF_R(24)  x0 += KS1; x1 += KS2 + 4u;
    TF_R(13) TF_R(15) TF_R(26) TF_R(6)   x0 += KS2; x1 += KS0 + 5u;
#undef TF_R
    o0 = x0; o1 = x1;
}

__device__ __forceinline__ float gumbel_from_bits(uint32_t bits) {
    float u = __uint_as_float((bits >> 9) | 0x3f800000u) - 1.0f;
    u = fmaxf(u, 1.17549435e-38f);  // jax uniform minval = tiny
    return -logf(-logf(u));
}

// ---------------- K3 (fused): softmax stats + gumbel-perturbed argmax, one row read ----
__global__ void __launch_bounds__(256) softmax_argmax_kernel() {
    const int n = blockIdx.x;
    const int tid = threadIdx.x;
    const float* row = g_L + (size_t)n * M_COLS;
    // each thread owns 8 contiguous elements: j = tid*8 + i
    float4 v0 = *(const float4*)(row + tid * 8);
    float4 v1 = *(const float4*)(row + tid * 8 + 4);
    float ev[8] = {v0.x, v0.y, v0.z, v0.w, v1.x, v1.y, v1.z, v1.w};

    __shared__ float sm[256];
    // --- row max ---
    float lmax = ev[0];
#pragma unroll
    for (int i = 1; i < 8; i++) lmax = fmaxf(lmax, ev[i]);
    sm[tid] = lmax;
    __syncthreads();
    for (int st = 128; st > 0; st >>= 1) {
        if (tid < st) sm[tid] = fmaxf(sm[tid], sm[tid + st]);
        __syncthreads();
    }
    float rmax = sm[0];
    __syncthreads();
    // --- row sum of exp ---
    float ls = 0.f;
#pragma unroll
    for (int i = 0; i < 8; i++) { ev[i] = expf(ev[i] - rmax); ls += ev[i]; }
    sm[tid] = ls;
    __syncthreads();
    for (int st = 128; st > 0; st >>= 1) {
        if (tid < st) sm[tid] += sm[tid + st];
        __syncthreads();
    }
    const float rZ = 1.0f / sm[0];
    __syncthreads();
    // --- argmax of p + gumbel ---
    float best = -3.4e38f;
    int bi = 0x7FFFFFFF;
    const uint32_t fbase = (uint32_t)(n * M_COLS) + (uint32_t)(tid * 8);
#pragma unroll
    for (int i = 0; i < 8; i++) {
        uint32_t o0, o1;
        threefry2x32_042(0u, fbase + (uint32_t)i, o0, o1);
        float s = ev[i] * rZ + gumbel_from_bits(o0 ^ o1);
        if (s > best) { best = s; bi = tid * 8 + i; }  // ascending j, '>' keeps first index
    }
    __shared__ int si[256];
    sm[tid] = best; si[tid] = bi;
    __syncthreads();
    for (int st = 128; st > 0; st >>= 1) {
        if (tid < st) {
            float v2 = sm[tid + st]; int i2 = si[tid + st];
            if (v2 > sm[tid] || (v2 == sm[tid] && i2 < si[tid])) { sm[tid] = v2; si[tid] = i2; }
        }
        __syncthreads();
    }
    if (tid == 0) g_idx[n] = si[0];
}

// ---------------- K5: acc = 0; acc[idx[n]] += x1[n] ----------------
__global__ void __launch_bounds__(256) zero_acc_kernel() {
    g_acc[blockIdx.x * 256 + threadIdx.x] = 0.f;
}

__global__ void __launch_bounds__(256) scatter_kernel(const float* __restrict__ x1) {
    const int w = threadIdx.x >> 5;
    const int lane = threadIdx.x & 31;
    const int n = blockIdx.x * 8 + w;
    const int m = g_idx[n];
#pragma unroll
    for (int i = 0; i < 4; i++) {
        int d = lane + i * 32;
        atomicAdd(&g_acc[m * DIM + d], x1[(size_t)n * DIM + d]);
    }
}

// ---------------- K6: out = acc @ Wd.T + bd ----------------
__global__ void __launch_bounds__(128) final_kernel(const float* __restrict__ Wd,
                                                    const float* __restrict__ bd,
                                                    float* __restrict__ out) {
    const int m = blockIdx.x;
    const int j = threadIdx.x;
    __shared__ float a[DIM];
    a[j] = g_acc[m * DIM + j];
    __syncthreads();
    float s = bd[j];
#pragma unroll 8
    for (int kq = 0; kq < DIM; kq++) s = fmaf(a[kq], Wd[j * DIM + kq], s);
    out[m * DIM + j] = s;
}

// ---------------- launch ----------------
extern "C" void kernel_launch(void* const* d_in, const int* in_sizes, int n_in,
                              void* d_out, int out_size) {
    const float* x1 = (const float*)d_in[0];
    const float* k  = (const float*)d_in[1];
    const float* c  = (const float*)d_in[2];
    const float* Wq = (const float*)d_in[3];
    const float* bq = (const float*)d_in[4];
    const float* Wd = (const float*)d_in[5];
    const float* bd = (const float*)d_in[6];
    float* out = (float*)d_out;

    prep_Wb_kernel<<<128, 128>>>(Wq, bq);
    prep_G_kernel<<<M_COLS, 128>>>(c);
    dim3 gl(M_COLS / BN, N_ROWS / BM);
    logits_kernel<<<gl, 256>>>(x1, k);
    softmax_argmax_kernel<<<N_ROWS, 256>>>();
    zero_acc_kernel<<<M_COLS * DIM / 256, 256>>>();
    scatter_kernel<<<N_ROWS / 8, 256>>>(x1);
    final_kernel<<<M_COLS, 128>>>(Wd, bd, out);
}